// round 13
// baseline (speedup 1.0000x reference)
#include <cuda_runtime.h>
#include <cuda_fp16.h>
#include <math.h>
#include <stdint.h>

#define NMAX  50000
#define EMAX  800000
#define NGR   128

#define TB_BINS  3072          // bins over [0, 1.5), step 1/2048
#define TB_ROWS  (TB_BINS + 1)
#define TB_SCALE 2048.0f
#define TB_DMAX  1.49951f

// ---------------- scratch (static device arrays: no allocations) ----------------
__device__ __half2 g_actA[(size_t)NMAX * 64];
__device__ __half2 g_actB[(size_t)NMAX * 64];
__device__ float   g_pool[NGR * 32];

// CSR by dst + packed edge records (CSR order), 32B each:
// u0 = { srcn, bin|xs<<16, h2(sh0,sh1), h2(sh2,sh3) }
// u1 = { h2(sh4,sh5), h2(sh6,sh7), h2(sh8,0), 0 }
__device__ int      g_cnt[NMAX];
__device__ int      g_off[NMAX];
__device__ int      g_pos[NMAX];
__device__ unsigned g_erec[(size_t)EMAX * 8];

// radial-weight tables (cutoff folded in), fp16 path-paired
__device__ __half2 g_tab1h[(size_t)TB_ROWS * 32];
__device__ __half2 g_tab2h[(size_t)TB_ROWS * 96];
__device__ __half2 g_tab3h[(size_t)TB_ROWS * 32];

// ---------------- helpers ----------------
__device__ __forceinline__ float sspf(float x) {
    return fmaxf(x, 0.f) + log1pf(__expf(-fabsf(x))) - 0.69314718055994530942f;
}
__device__ __forceinline__ float cutoff_w(float d) {
    float u = d * (1.0f / 1.5f);
    if (u >= 1.f) return 0.f;
    float u2v = u * u;
    float u6 = u2v * u2v * u2v;
    return 1.f + u6 * (-28.f + u * (48.f - 21.f * u));
}
__device__ __forceinline__ float2 h2f(unsigned bits) {
    __half2 h = *reinterpret_cast<__half2*>(&bits);
    return __half22float2(h);
}

// ---------------- table generation (emb/cutoff inline) ----------------
// per_row = 32(t1) + 96(t2) + 32(t3) = 160
__global__ void k_tab_build_all(
    const float* __restrict__ W1, const float* __restrict__ b1,
    const float* __restrict__ W2, const float* __restrict__ b2,
    const float* __restrict__ W3, const float* __restrict__ b3)
{
    int t = blockIdx.x * blockDim.x + threadIdx.x;
    if (t >= TB_ROWS * 160) return;
    int r = t / 160, rem = t - r * 160;

    float d = (float)r * (1.0f / TB_SCALE);
    float ew = cutoff_w(d);
    float emb[10];
    #pragma unroll
    for (int k = 0; k < 10; k++) {
        float mu = 0.7f + (float)k * 0.111111111111111111f;
        float dd = d - mu;
        emb[k] = __expf(-50.f * dd * dd);
    }

    const float* W; const float* b; __half2* out; int C; int pp; int lane; int oidx;
    if (rem < 32)       { W = W1; b = b1; C = 64;  pp = 0;               lane = rem;      out = g_tab1h; oidx = r * 32 + rem; }
    else if (rem < 128) { W = W2; b = b2; C = 192; pp = (rem - 32) >> 5; lane = rem & 31; out = g_tab2h; oidx = r * 96 + (rem - 32); }
    else                { W = W3; b = b3; C = 64;  pp = 0;               lane = rem & 31; out = g_tab3h; oidx = r * 32 + (rem - 128); }

    int c0 = (2 * pp) * 32 + lane;
    int c1 = (2 * pp + 1) * 32 + lane;
    float v0 = b[c0], v1 = b[c1];
    #pragma unroll
    for (int k = 0; k < 10; k++) {
        v0 = fmaf(emb[k], W[k * C + c0], v0);
        v1 = fmaf(emb[k], W[k * C + c1], v1);
    }
    out[oidx] = __floats2half2_rn(v0 * ew, v1 * ew);
}

// ---------------- CSR build ----------------
__global__ void k_hist(const int* __restrict__ ei, int E)
{
    int e = blockIdx.x * blockDim.x + threadIdx.x;
    if (e < NGR * 32) g_pool[e] = 0.f;          // fold pool zeroing in here
    if (e < E) atomicAdd(&g_cnt[ei[E + e]], 1);
}

// single-block fused exclusive scan: g_cnt -> g_off, g_pos
__global__ void k_scan_fused(int n)
{
    __shared__ int wsum[32];
    int tid = threadIdx.x, lane = tid & 31, wid = tid >> 5;
    int carry = 0;
    for (int base = 0; base < n; base += 1024) {
        int gid = base + tid;
        int v = (gid < n) ? g_cnt[gid] : 0;
        int s = v;
        #pragma unroll
        for (int o = 1; o < 32; o <<= 1) {
            int t2 = __shfl_up_sync(0xffffffffu, s, o);
            if (lane >= o) s += t2;
        }
        if (lane == 31) wsum[wid] = s;
        __syncthreads();
        if (wid == 0) {
            int ws = wsum[lane];
            #pragma unroll
            for (int o = 1; o < 32; o <<= 1) {
                int t2 = __shfl_up_sync(0xffffffffu, ws, o);
                if (lane >= o) ws += t2;
            }
            wsum[lane] = ws;
        }
        __syncthreads();
        int excl = s - v + (wid ? wsum[wid - 1] : 0) + carry;
        if (gid < n) { g_off[gid] = excl; g_pos[gid] = excl; }
        carry += wsum[31];
        __syncthreads();
    }
}

// scatter + build packed 32B record at CSR slot
__global__ void k_scatter(const int* __restrict__ ei, const float* __restrict__ elen,
                          const float* __restrict__ esh, const float* __restrict__ x, int E)
{
    int e = blockIdx.x * blockDim.x + threadIdx.x;
    if (e >= E) return;
    int d = ei[E + e];
    int p = atomicAdd(&g_pos[d], 1);
    int s = ei[e];
    float dd = elen[e];
    float tt = fminf(fmaxf(dd, 0.f), TB_DMAX) * TB_SCALE;
    unsigned bin = (unsigned)(int)(tt + 0.5f);
    const float* sh = esh + (size_t)e * 9;

    __half xsh = __float2half_rn(x[s]);
    unsigned w1 = bin | ((unsigned)__half_as_ushort(xsh) << 16);
    __half2 p01 = __floats2half2_rn(sh[0], sh[1]);
    __half2 p23 = __floats2half2_rn(sh[2], sh[3]);
    __half2 p45 = __floats2half2_rn(sh[4], sh[5]);
    __half2 p67 = __floats2half2_rn(sh[6], sh[7]);
    __half2 p8z = __floats2half2_rn(sh[8], 0.f);

    uint4 u0 = make_uint4((unsigned)s, w1,
                          *reinterpret_cast<unsigned*>(&p01),
                          *reinterpret_cast<unsigned*>(&p23));
    uint4 u1 = make_uint4(*reinterpret_cast<unsigned*>(&p45),
                          *reinterpret_cast<unsigned*>(&p67),
                          *reinterpret_cast<unsigned*>(&p8z), 0u);
    uint4* out = (uint4*)(g_erec + (size_t)p * 8);
    out[0] = u0; out[1] = u1;
}

// ---------------- feature fetch / write ----------------
__device__ __forceinline__ void gather_feat(const __half2* base, int node, int lane,
                                            float& x0, float& xv0, float& xv1, float& xv2)
{
    const uint2* p = (const uint2*)(base + (size_t)node * 64 + lane * 2);
    uint2 raw = __ldg(p);
    float2 f01 = h2f(raw.x);
    float2 f23 = h2f(raw.y);
    x0 = f01.x; xv0 = f01.y; xv1 = f23.x; xv2 = f23.y;
}

__device__ __forceinline__ void write_normact(__half2* base, int node, int lane,
                                              float s, float v0, float v1, float v2)
{
    float nr = sqrtf(v0 * v0 + v1 * v1 + v2 * v2 + 1e-12f);
    float sc = sspf(nr) / nr;
    uint2 o;
    __half2 h01 = __floats2half2_rn(sspf(s), v0 * sc);
    __half2 h23 = __floats2half2_rn(v1 * sc, v2 * sc);
    o.x = *reinterpret_cast<unsigned*>(&h01);
    o.y = *reinterpret_cast<unsigned*>(&h23);
    *(uint2*)(base + (size_t)node * 64 + lane * 2) = o;
}

// ---------------- layer-1 edge op ----------------
__device__ __forceinline__ void l1_edge(uint4 u0, int lane,
                                        float& a0, float& a1, float& a2, float& a3)
{
    int bin = (int)(u0.y & 0xFFFFu);
    float xs = __half2float(__ushort_as_half((unsigned short)(u0.y >> 16)));
    float2 s01 = h2f(u0.z);
    float2 s23 = h2f(u0.w);
    float2 wv = __half22float2(__ldg(g_tab1h + (size_t)bin * 32 + lane));
    float xw0 = xs * wv.x;
    float xw1 = xs * wv.y;
    a0 += xw0 * s01.x;
    a1 += xw1 * s01.y;
    a2 += xw1 * s23.x;
    a3 += xw1 * s23.y;
}

// ---------------- layer 1 (dst-major, dual chain, fused norm-act) ----------------
__global__ void __launch_bounds__(256) k_layer1(int E, int N)
{
    int node = (blockIdx.x * blockDim.x + threadIdx.x) >> 5;
    if (node >= N) return;
    int lane = threadIdx.x & 31;
    int beg = __ldg(&g_off[node]);
    int end = (node + 1 < N) ? __ldg(&g_off[node + 1]) : E;
    int cnt = end - beg, half = cnt >> 1;

    float a0 = 0.f, a1 = 0.f, a2 = 0.f, a3 = 0.f;
    float c0 = 0.f, c1 = 0.f, c2 = 0.f, c3 = 0.f;
    for (int k = 0; k < half; k++) {
        uint4 uA = __ldg((const uint4*)(g_erec + (size_t)(beg + k) * 8));
        uint4 uB = __ldg((const uint4*)(g_erec + (size_t)(beg + half + k) * 8));
        l1_edge(uA, lane, a0, a1, a2, a3);
        l1_edge(uB, lane, c0, c1, c2, c3);
    }
    if (cnt & 1) {
        uint4 uA = __ldg((const uint4*)(g_erec + (size_t)(end - 1) * 8));
        l1_edge(uA, lane, a0, a1, a2, a3);
    }
    write_normact(g_actA, node, lane, a0 + c0, a1 + c1, a2 + c2, a3 + c3);
}

// ---------------- layer 2 (dst-major, prefetch, fused norm-act) ----------------
__global__ void __launch_bounds__(256) k_layer2(int E, int N)
{
    int node = (blockIdx.x * blockDim.x + threadIdx.x) >> 5;
    if (node >= N) return;
    int lane = threadIdx.x & 31;
    int beg = __ldg(&g_off[node]);
    int end = (node + 1 < N) ? __ldg(&g_off[node + 1]) : E;

    const float RT3I = 0.57735026918962576451f;  // 1/sqrt(3)
    const float RT2I = 0.70710678118654752440f;  // 1/sqrt(2)
    const float A    = 0.31622776601683793320f;  // 1/sqrt(10)
    const float B    = 0.54772255750516611346f;  // sqrt(3/10)

    float a0 = 0.f, a1 = 0.f, a2 = 0.f, a3 = 0.f;
    uint4 u0, u1;
    if (beg < end) {
        const uint4* rp = (const uint4*)(g_erec + (size_t)beg * 8);
        u0 = __ldg(rp); u1 = __ldg(rp + 1);
    }
    for (int i = beg; i < end; i++) {
        uint4 v0 = u0, v1 = u1;
        int nx = (i + 1 < end) ? (i + 1) : i;          // prefetch next record
        const uint4* rp = (const uint4*)(g_erec + (size_t)nx * 8);
        u0 = __ldg(rp); u1 = __ldg(rp + 1);

        int srcn = (int)v0.x;
        int bin  = (int)(v0.y & 0xFFFFu);

        float x0, xv0, xv1, xv2;
        gather_feat(g_actA, srcn, lane, x0, xv0, xv1, xv2);

        const __half2* tb = g_tab2h + (size_t)bin * 96 + lane;
        float2 w01 = __half22float2(__ldg(tb));
        float2 w23 = __half22float2(__ldg(tb + 32));
        float2 w45 = __half22float2(__ldg(tb + 64));

        float2 s01 = h2f(v0.z);
        float2 s23 = h2f(v0.w);
        float2 s45 = h2f(v1.x);
        float2 s67 = h2f(v1.y);
        float2 s8z = h2f(v1.z);
        float s0  = s01.x;
        float sv0 = s01.y, sv1 = s23.x, sv2 = s23.y;
        float t20 = s45.x, t21 = s45.y, t22 = s67.x, t23 = s67.y, t24 = s8z.x;

        // paths (0,0,0) + (1,1,0)
        float dotv = xv0 * sv0 + xv1 * sv1 + xv2 * sv2;
        float m0 = s0 * x0 * w01.x - RT3I * dotv * w23.y;

        // path (1,1,1): -1/sqrt2 * cross
        float cr0 = xv1 * sv2 - xv2 * sv1;
        float cr1 = xv2 * sv0 - xv0 * sv2;
        float cr2 = xv0 * sv1 - xv1 * sv0;

        // path (1,2,1): real CG(1,2,1) contraction
        float t50 =  A * xv0 * t22 + B * xv0 * t24 - B * xv1 * t21 - B * xv2 * t20;
        float t51 = -B * xv0 * t21 - 2.f * A * xv1 * t22 - B * xv2 * t23;
        float t52 = -B * xv0 * t20 - B * xv1 * t23 + A * xv2 * t22 - B * xv2 * t24;

        float x0w1 = x0 * w01.y;
        float s0w2 = s0 * w23.x;
        float wn4  = -RT2I * w45.x;
        a0 += m0;
        a1 += sv0 * x0w1 + xv0 * s0w2 + cr0 * wn4 + t50 * w45.y;
        a2 += sv1 * x0w1 + xv1 * s0w2 + cr1 * wn4 + t51 * w45.y;
        a3 += sv2 * x0w1 + xv2 * s0w2 + cr2 * wn4 + t52 * w45.y;
    }
    write_normact(g_actB, node, lane, a0, a1, a2, a3);
}

// ---------------- layer-3 edge op ----------------
__device__ __forceinline__ void l3_edge(uint4 u0, int lane, float& h)
{
    const float RT3I = 0.57735026918962576451f;
    int srcn = (int)u0.x;
    int bin  = (int)(u0.y & 0xFFFFu);
    float x0, xv0, xv1, xv2;
    gather_feat(g_actB, srcn, lane, x0, xv0, xv1, xv2);
    float2 wv = __half22float2(__ldg(g_tab3h + (size_t)bin * 32 + lane));
    float2 s01 = h2f(u0.z);
    float2 s23 = h2f(u0.w);
    float dotv = xv0 * s01.y + xv1 * s23.x + xv2 * s23.y;
    h += x0 * s01.x * wv.x - RT3I * dotv * wv.y;
}

// ---------------- layer 3 (dst-major, dual chain) + silu + pool ----------------
__global__ void __launch_bounds__(256) k_layer3(const int* __restrict__ batch, int E, int N)
{
    int node = (blockIdx.x * blockDim.x + threadIdx.x) >> 5;
    if (node >= N) return;
    int lane = threadIdx.x & 31;
    int beg = __ldg(&g_off[node]);
    int end = (node + 1 < N) ? __ldg(&g_off[node + 1]) : E;
    int cnt = end - beg, half = cnt >> 1;

    float ha = 0.f, hb = 0.f;
    for (int k = 0; k < half; k++) {
        uint4 uA = __ldg((const uint4*)(g_erec + (size_t)(beg + k) * 8));
        uint4 uB = __ldg((const uint4*)(g_erec + (size_t)(beg + half + k) * 8));
        l3_edge(uA, lane, ha);
        l3_edge(uB, lane, hb);
    }
    if (cnt & 1) {
        uint4 uA = __ldg((const uint4*)(g_erec + (size_t)(end - 1) * 8));
        l3_edge(uA, lane, ha);
    }
    float h = ha + hb;
    float y = h / (1.f + __expf(-h));   // silu
    atomicAdd(&g_pool[__ldg(&batch[node]) * 32 + lane], y);
}

// ---------------- head ----------------
__global__ void k_head(const float* __restrict__ Wo, const float* __restrict__ bo,
                       float* __restrict__ out)
{
    __shared__ float Ws[32 * 8];
    __shared__ float bs[8];
    int t = threadIdx.x;
    if (t < 256) Ws[t] = Wo[t];
    if (t < 8)   bs[t] = bo[t];
    __syncthreads();
    if (t < NGR) {
        float acc[8];
        #pragma unroll
        for (int j = 0; j < 8; j++) acc[j] = bs[j];
        #pragma unroll
        for (int k = 0; k < 32; k++) {
            float gv = g_pool[t * 32 + k];
            #pragma unroll
            for (int j = 0; j < 8; j++) acc[j] = fmaf(gv, Ws[k * 8 + j], acc[j]);
        }
        float mx = acc[0];
        #pragma unroll
        for (int j = 1; j < 8; j++) mx = fmaxf(mx, acc[j]);
        float sm = 0.f;
        #pragma unroll
        for (int j = 0; j < 8; j++) { acc[j] = __expf(acc[j] - mx); sm += acc[j]; }
        float inv = 1.f / sm;
        #pragma unroll
        for (int j = 0; j < 8; j++) out[t * 8 + j] = acc[j] * inv;
    }
}

// ---------------- host ----------------
extern "C" void kernel_launch(void* const* d_in, const int* in_sizes, int n_in,
                              void* d_out, int out_size)
{
    int ix, ish, ilen, iW1, ib1, iW2, ib2, iW3, ib3, iWo, ibo, iei, ibatch;
    if (n_in >= 13 && (long long)in_sizes[1] == 9LL * (long long)in_sizes[2]) {
        ix = 0; ish = 1; ilen = 2; iW1 = 3; ib1 = 4; iW2 = 5; ib2 = 6;
        iW3 = 7; ib3 = 8; iWo = 9; ibo = 10; iei = 11; ibatch = 12;
    } else {
        ix = 0; iei = 1; ish = 2; ilen = 3; ibatch = 4; iW1 = 5; ib1 = 6;
        iW2 = 7; ib2 = 8; iW3 = 9; ib3 = 10; iWo = 11; ibo = 12;
    }

    const float* x     = (const float*)d_in[ix];
    const float* esh   = (const float*)d_in[ish];
    const float* elen  = (const float*)d_in[ilen];
    const float* W1    = (const float*)d_in[iW1];
    const float* b1    = (const float*)d_in[ib1];
    const float* W2    = (const float*)d_in[iW2];
    const float* b2    = (const float*)d_in[ib2];
    const float* W3    = (const float*)d_in[iW3];
    const float* b3    = (const float*)d_in[ib3];
    const float* Wo    = (const float*)d_in[iWo];
    const float* bo    = (const float*)d_in[ibo];
    const int*   ei    = (const int*)d_in[iei];
    const int*   batch = (const int*)d_in[ibatch];

    int N = in_sizes[ix];
    int E = in_sizes[ilen];
    if (N > NMAX) N = NMAX;
    if (E > EMAX) E = EMAX;

    void* pcnt;
    cudaGetSymbolAddress(&pcnt, g_cnt);

    int nbE = (E + 255) / 256;
    int nbW = (N * 32 + 255) / 256;

    // Radial-weight tables (emb/cutoff inline, cutoff folded in)
    k_tab_build_all<<<(TB_ROWS * 160 + 255) / 256, 256>>>(W1, b1, W2, b2, W3, b3);

    // CSR by dst + packed records
    cudaMemsetAsync(pcnt, 0, (size_t)N * sizeof(int), 0);
    k_hist<<<nbE, 256>>>(ei, E);            // also zeroes g_pool
    k_scan_fused<<<1, 1024>>>(N);
    k_scatter<<<nbE, 256>>>(ei, elen, esh, x, E);

    // Layers (dst-major, fused norm-act)
    k_layer1<<<nbW, 256>>>(E, N);
    k_layer2<<<nbW, 256>>>(E, N);
    k_layer3<<<nbW, 256>>>(batch, E, N);
    k_head<<<1, 256>>>(Wo, bo, (float*)d_out);
}

// round 14
// speedup vs baseline: 1.2202x; 1.2202x over previous
#include <cuda_runtime.h>
#include <cuda_fp16.h>
#include <math.h>
#include <stdint.h>

#define NMAX  50000
#define EMAX  800000
#define NGR   128

#define TB_BINS  3072          // bins over [0, 1.5), step 1/2048
#define TB_ROWS  (TB_BINS + 1)
#define TB_SCALE 2048.0f
#define TB_DMAX  1.49951f

#define SCAN_B 256

// ---------------- scratch (static device arrays: no allocations) ----------------
__device__ __half2 g_actA[(size_t)NMAX * 64];
__device__ __half2 g_actB[(size_t)NMAX * 64];
__device__ float   g_pool[NGR * 32];

// CSR by dst + packed edge records (CSR order), 32B each:
// u0 = { srcn, bin|xs<<16, h2(sh0,sh1), h2(sh2,sh3) }
// u1 = { h2(sh4,sh5), h2(sh6,sh7), h2(sh8,0), 0 }
__device__ int      g_cnt[NMAX];
__device__ int      g_off[NMAX];
__device__ int      g_pos[NMAX];
__device__ unsigned g_erec[(size_t)EMAX * 8];
__device__ int      g_bsum[(NMAX + SCAN_B - 1) / SCAN_B + 1];

// radial-weight tables (cutoff folded in), fp16 path-paired
__device__ __half2 g_tab1h[(size_t)TB_ROWS * 32];
__device__ __half2 g_tab2h[(size_t)TB_ROWS * 96];
__device__ __half2 g_tab3h[(size_t)TB_ROWS * 32];

// ---------------- helpers ----------------
__device__ __forceinline__ float sspf(float x) {
    return fmaxf(x, 0.f) + log1pf(__expf(-fabsf(x))) - 0.69314718055994530942f;
}
__device__ __forceinline__ float cutoff_w(float d) {
    float u = d * (1.0f / 1.5f);
    if (u >= 1.f) return 0.f;
    float u2v = u * u;
    float u6 = u2v * u2v * u2v;
    return 1.f + u6 * (-28.f + u * (48.f - 21.f * u));
}
__device__ __forceinline__ float2 h2f(unsigned bits) {
    __half2 h = *reinterpret_cast<__half2*>(&bits);
    return __half22float2(h);
}

// ---------------- table generation (emb/cutoff inline) ----------------
// per_row = 32(t1) + 96(t2) + 32(t3) = 160
__global__ void k_tab_build_all(
    const float* __restrict__ W1, const float* __restrict__ b1,
    const float* __restrict__ W2, const float* __restrict__ b2,
    const float* __restrict__ W3, const float* __restrict__ b3)
{
    int t = blockIdx.x * blockDim.x + threadIdx.x;
    if (t >= TB_ROWS * 160) return;
    int r = t / 160, rem = t - r * 160;

    float d = (float)r * (1.0f / TB_SCALE);
    float ew = cutoff_w(d);
    float emb[10];
    #pragma unroll
    for (int k = 0; k < 10; k++) {
        float mu = 0.7f + (float)k * 0.111111111111111111f;
        float dd = d - mu;
        emb[k] = __expf(-50.f * dd * dd);
    }

    const float* W; const float* b; __half2* out; int C; int pp; int lane; int oidx;
    if (rem < 32)       { W = W1; b = b1; C = 64;  pp = 0;               lane = rem;      out = g_tab1h; oidx = r * 32 + rem; }
    else if (rem < 128) { W = W2; b = b2; C = 192; pp = (rem - 32) >> 5; lane = rem & 31; out = g_tab2h; oidx = r * 96 + (rem - 32); }
    else                { W = W3; b = b3; C = 64;  pp = 0;               lane = rem & 31; out = g_tab3h; oidx = r * 32 + (rem - 128); }

    int c0 = (2 * pp) * 32 + lane;
    int c1 = (2 * pp + 1) * 32 + lane;
    float v0 = b[c0], v1 = b[c1];
    #pragma unroll
    for (int k = 0; k < 10; k++) {
        v0 = fmaf(emb[k], W[k * C + c0], v0);
        v1 = fmaf(emb[k], W[k * C + c1], v1);
    }
    out[oidx] = __floats2half2_rn(v0 * ew, v1 * ew);
}

// ---------------- CSR build ----------------
__global__ void k_hist(const int* __restrict__ ei, int E)
{
    int e = blockIdx.x * blockDim.x + threadIdx.x;
    if (e < NGR * 32) g_pool[e] = 0.f;          // fold pool zeroing in here
    if (e < E) atomicAdd(&g_cnt[ei[E + e]], 1);
}

// scan1: per-block exclusive scan of g_cnt -> g_off (block-local), block total -> g_bsum
__global__ void k_scan1(int n)
{
    __shared__ int sh[SCAN_B];
    int gid = blockIdx.x * SCAN_B + threadIdx.x;
    int v = (gid < n) ? g_cnt[gid] : 0;
    sh[threadIdx.x] = v;
    __syncthreads();
    #pragma unroll
    for (int ofs = 1; ofs < SCAN_B; ofs <<= 1) {
        int t = (threadIdx.x >= ofs) ? sh[threadIdx.x - ofs] : 0;
        __syncthreads();
        sh[threadIdx.x] += t;
        __syncthreads();
    }
    if (gid < n) g_off[gid] = sh[threadIdx.x] - v;
    if (threadIdx.x == SCAN_B - 1) g_bsum[blockIdx.x] = sh[SCAN_B - 1];
}

// scan23: each block reduces preceding block sums itself, applies offset
__global__ void k_scan23(int n)
{
    __shared__ int warp_part[8];
    int nb = blockIdx.x;           // number of preceding blocks
    int acc = 0;
    for (int i = threadIdx.x; i < nb; i += SCAN_B) acc += g_bsum[i];
    // block reduce
    #pragma unroll
    for (int o = 16; o > 0; o >>= 1) acc += __shfl_down_sync(0xffffffffu, acc, o);
    if ((threadIdx.x & 31) == 0) warp_part[threadIdx.x >> 5] = acc;
    __syncthreads();
    if (threadIdx.x == 0) {
        int s = 0;
        #pragma unroll
        for (int w = 0; w < 8; w++) s += warp_part[w];
        warp_part[0] = s;
    }
    __syncthreads();
    int blockOfs = warp_part[0];
    int gid = blockIdx.x * SCAN_B + threadIdx.x;
    if (gid < n) {
        int o = g_off[gid] + blockOfs;
        g_off[gid] = o;
        g_pos[gid] = o;
    }
}

// scatter + build packed 32B record at CSR slot
__global__ void k_scatter(const int* __restrict__ ei, const float* __restrict__ elen,
                          const float* __restrict__ esh, const float* __restrict__ x, int E)
{
    int e = blockIdx.x * blockDim.x + threadIdx.x;
    if (e >= E) return;
    int d = ei[E + e];
    int p = atomicAdd(&g_pos[d], 1);
    int s = ei[e];
    float dd = elen[e];
    float tt = fminf(fmaxf(dd, 0.f), TB_DMAX) * TB_SCALE;
    unsigned bin = (unsigned)(int)(tt + 0.5f);
    const float* sh = esh + (size_t)e * 9;

    __half xsh = __float2half_rn(x[s]);
    unsigned w1 = bin | ((unsigned)__half_as_ushort(xsh) << 16);
    __half2 p01 = __floats2half2_rn(sh[0], sh[1]);
    __half2 p23 = __floats2half2_rn(sh[2], sh[3]);
    __half2 p45 = __floats2half2_rn(sh[4], sh[5]);
    __half2 p67 = __floats2half2_rn(sh[6], sh[7]);
    __half2 p8z = __floats2half2_rn(sh[8], 0.f);

    uint4 u0 = make_uint4((unsigned)s, w1,
                          *reinterpret_cast<unsigned*>(&p01),
                          *reinterpret_cast<unsigned*>(&p23));
    uint4 u1 = make_uint4(*reinterpret_cast<unsigned*>(&p45),
                          *reinterpret_cast<unsigned*>(&p67),
                          *reinterpret_cast<unsigned*>(&p8z), 0u);
    uint4* out = (uint4*)(g_erec + (size_t)p * 8);
    out[0] = u0; out[1] = u1;
}

// ---------------- feature fetch / write ----------------
__device__ __forceinline__ void gather_feat(const __half2* base, int node, int lane,
                                            float& x0, float& xv0, float& xv1, float& xv2)
{
    const uint2* p = (const uint2*)(base + (size_t)node * 64 + lane * 2);
    uint2 raw = __ldg(p);
    float2 f01 = h2f(raw.x);
    float2 f23 = h2f(raw.y);
    x0 = f01.x; xv0 = f01.y; xv1 = f23.x; xv2 = f23.y;
}

__device__ __forceinline__ void write_normact(__half2* base, int node, int lane,
                                              float s, float v0, float v1, float v2)
{
    float nr = sqrtf(v0 * v0 + v1 * v1 + v2 * v2 + 1e-12f);
    float sc = sspf(nr) / nr;
    uint2 o;
    __half2 h01 = __floats2half2_rn(sspf(s), v0 * sc);
    __half2 h23 = __floats2half2_rn(v1 * sc, v2 * sc);
    o.x = *reinterpret_cast<unsigned*>(&h01);
    o.y = *reinterpret_cast<unsigned*>(&h23);
    *(uint2*)(base + (size_t)node * 64 + lane * 2) = o;
}

// ---------------- layer 1 (dst-major, fused norm-act) ----------------
__global__ void __launch_bounds__(256) k_layer1(int E, int N)
{
    int node = (blockIdx.x * blockDim.x + threadIdx.x) >> 5;
    if (node >= N) return;
    int lane = threadIdx.x & 31;
    int beg = __ldg(&g_off[node]);
    int end = (node + 1 < N) ? __ldg(&g_off[node + 1]) : E;

    float a0 = 0.f, a1 = 0.f, a2 = 0.f, a3 = 0.f;
    #pragma unroll 2
    for (int i = beg; i < end; i++) {
        uint4 u0 = __ldg((const uint4*)(g_erec + (size_t)i * 8));
        int bin = (int)(u0.y & 0xFFFFu);
        float xs = __half2float(__ushort_as_half((unsigned short)(u0.y >> 16)));
        float2 s01 = h2f(u0.z);
        float2 s23 = h2f(u0.w);
        float2 wv = __half22float2(__ldg(g_tab1h + (size_t)bin * 32 + lane));
        float xw0 = xs * wv.x;
        float xw1 = xs * wv.y;
        a0 += xw0 * s01.x;
        a1 += xw1 * s01.y;
        a2 += xw1 * s23.x;
        a3 += xw1 * s23.y;
    }
    write_normact(g_actA, node, lane, a0, a1, a2, a3);
}

// ---------------- layer 2 (dst-major, fused norm-act) ----------------
__global__ void __launch_bounds__(256) k_layer2(int E, int N)
{
    int node = (blockIdx.x * blockDim.x + threadIdx.x) >> 5;
    if (node >= N) return;
    int lane = threadIdx.x & 31;
    int beg = __ldg(&g_off[node]);
    int end = (node + 1 < N) ? __ldg(&g_off[node + 1]) : E;

    const float RT3I = 0.57735026918962576451f;  // 1/sqrt(3)
    const float RT2I = 0.70710678118654752440f;  // 1/sqrt(2)
    const float A    = 0.31622776601683793320f;  // 1/sqrt(10)
    const float B    = 0.54772255750516611346f;  // sqrt(3/10)

    float a0 = 0.f, a1 = 0.f, a2 = 0.f, a3 = 0.f;
    #pragma unroll 2
    for (int i = beg; i < end; i++) {
        const uint4* rp = (const uint4*)(g_erec + (size_t)i * 8);
        uint4 u0 = __ldg(rp);
        uint4 u1 = __ldg(rp + 1);
        int srcn = (int)u0.x;
        int bin  = (int)(u0.y & 0xFFFFu);

        float x0, xv0, xv1, xv2;
        gather_feat(g_actA, srcn, lane, x0, xv0, xv1, xv2);

        const __half2* tb = g_tab2h + (size_t)bin * 96 + lane;
        float2 w01 = __half22float2(__ldg(tb));
        float2 w23 = __half22float2(__ldg(tb + 32));
        float2 w45 = __half22float2(__ldg(tb + 64));

        float2 s01 = h2f(u0.z);
        float2 s23 = h2f(u0.w);
        float2 s45 = h2f(u1.x);
        float2 s67 = h2f(u1.y);
        float2 s8z = h2f(u1.z);
        float s0  = s01.x;
        float sv0 = s01.y, sv1 = s23.x, sv2 = s23.y;
        float t20 = s45.x, t21 = s45.y, t22 = s67.x, t23 = s67.y, t24 = s8z.x;

        // paths (0,0,0) + (1,1,0)
        float dotv = xv0 * sv0 + xv1 * sv1 + xv2 * sv2;
        float m0 = s0 * x0 * w01.x - RT3I * dotv * w23.y;

        // path (1,1,1): -1/sqrt2 * cross
        float cr0 = xv1 * sv2 - xv2 * sv1;
        float cr1 = xv2 * sv0 - xv0 * sv2;
        float cr2 = xv0 * sv1 - xv1 * sv0;

        // path (1,2,1): real CG(1,2,1) contraction
        float t50 =  A * xv0 * t22 + B * xv0 * t24 - B * xv1 * t21 - B * xv2 * t20;
        float t51 = -B * xv0 * t21 - 2.f * A * xv1 * t22 - B * xv2 * t23;
        float t52 = -B * xv0 * t20 - B * xv1 * t23 + A * xv2 * t22 - B * xv2 * t24;

        float x0w1 = x0 * w01.y;
        float s0w2 = s0 * w23.x;
        float wn4  = -RT2I * w45.x;
        a0 += m0;
        a1 += sv0 * x0w1 + xv0 * s0w2 + cr0 * wn4 + t50 * w45.y;
        a2 += sv1 * x0w1 + xv1 * s0w2 + cr1 * wn4 + t51 * w45.y;
        a3 += sv2 * x0w1 + xv2 * s0w2 + cr2 * wn4 + t52 * w45.y;
    }
    write_normact(g_actB, node, lane, a0, a1, a2, a3);
}

// ---------------- layer 3 (dst-major) + silu + pool ----------------
__global__ void __launch_bounds__(256) k_layer3(const int* __restrict__ batch, int E, int N)
{
    int node = (blockIdx.x * blockDim.x + threadIdx.x) >> 5;
    if (node >= N) return;
    int lane = threadIdx.x & 31;
    int beg = __ldg(&g_off[node]);
    int end = (node + 1 < N) ? __ldg(&g_off[node + 1]) : E;

    const float RT3I = 0.57735026918962576451f;
    float h = 0.f;
    #pragma unroll 2
    for (int i = beg; i < end; i++) {
        uint4 u0 = __ldg((const uint4*)(g_erec + (size_t)i * 8));
        int srcn = (int)u0.x;
        int bin  = (int)(u0.y & 0xFFFFu);

        float x0, xv0, xv1, xv2;
        gather_feat(g_actB, srcn, lane, x0, xv0, xv1, xv2);
        float2 wv = __half22float2(__ldg(g_tab3h + (size_t)bin * 32 + lane));

        float2 s01 = h2f(u0.z);
        float2 s23 = h2f(u0.w);
        float dotv = xv0 * s01.y + xv1 * s23.x + xv2 * s23.y;
        h += x0 * s01.x * wv.x - RT3I * dotv * wv.y;
    }
    float y = h / (1.f + __expf(-h));   // silu
    atomicAdd(&g_pool[__ldg(&batch[node]) * 32 + lane], y);
}

// ---------------- head ----------------
__global__ void k_head(const float* __restrict__ Wo, const float* __restrict__ bo,
                       float* __restrict__ out)
{
    __shared__ float Ws[32 * 8];
    __shared__ float bs[8];
    int t = threadIdx.x;
    if (t < 256) Ws[t] = Wo[t];
    if (t < 8)   bs[t] = bo[t];
    __syncthreads();
    if (t < NGR) {
        float acc[8];
        #pragma unroll
        for (int j = 0; j < 8; j++) acc[j] = bs[j];
        #pragma unroll
        for (int k = 0; k < 32; k++) {
            float gv = g_pool[t * 32 + k];
            #pragma unroll
            for (int j = 0; j < 8; j++) acc[j] = fmaf(gv, Ws[k * 8 + j], acc[j]);
        }
        float mx = acc[0];
        #pragma unroll
        for (int j = 1; j < 8; j++) mx = fmaxf(mx, acc[j]);
        float sm = 0.f;
        #pragma unroll
        for (int j = 0; j < 8; j++) { acc[j] = __expf(acc[j] - mx); sm += acc[j]; }
        float inv = 1.f / sm;
        #pragma unroll
        for (int j = 0; j < 8; j++) out[t * 8 + j] = acc[j] * inv;
    }
}

// ---------------- host ----------------
extern "C" void kernel_launch(void* const* d_in, const int* in_sizes, int n_in,
                              void* d_out, int out_size)
{
    int ix, ish, ilen, iW1, ib1, iW2, ib2, iW3, ib3, iWo, ibo, iei, ibatch;
    if (n_in >= 13 && (long long)in_sizes[1] == 9LL * (long long)in_sizes[2]) {
        ix = 0; ish = 1; ilen = 2; iW1 = 3; ib1 = 4; iW2 = 5; ib2 = 6;
        iW3 = 7; ib3 = 8; iWo = 9; ibo = 10; iei = 11; ibatch = 12;
    } else {
        ix = 0; iei = 1; ish = 2; ilen = 3; ibatch = 4; iW1 = 5; ib1 = 6;
        iW2 = 7; ib2 = 8; iW3 = 9; ib3 = 10; iWo = 11; ibo = 12;
    }

    const float* x     = (const float*)d_in[ix];
    const float* esh   = (const float*)d_in[ish];
    const float* elen  = (const float*)d_in[ilen];
    const float* W1    = (const float*)d_in[iW1];
    const float* b1    = (const float*)d_in[ib1];
    const float* W2    = (const float*)d_in[iW2];
    const float* b2    = (const float*)d_in[ib2];
    const float* W3    = (const float*)d_in[iW3];
    const float* b3    = (const float*)d_in[ib3];
    const float* Wo    = (const float*)d_in[iWo];
    const float* bo    = (const float*)d_in[ibo];
    const int*   ei    = (const int*)d_in[iei];
    const int*   batch = (const int*)d_in[ibatch];

    int N = in_sizes[ix];
    int E = in_sizes[ilen];
    if (N > NMAX) N = NMAX;
    if (E > EMAX) E = EMAX;

    void* pcnt;
    cudaGetSymbolAddress(&pcnt, g_cnt);

    int nbE = (E + 255) / 256;
    int nbS = (N + SCAN_B - 1) / SCAN_B;
    int nbW = (N * 32 + 255) / 256;

    // Radial-weight tables (emb/cutoff inline, cutoff folded in)
    k_tab_build_all<<<(TB_ROWS * 160 + 255) / 256, 256>>>(W1, b1, W2, b2, W3, b3);

    // CSR by dst + packed records
    cudaMemsetAsync(pcnt, 0, (size_t)N * sizeof(int), 0);
    k_hist<<<nbE, 256>>>(ei, E);            // also zeroes g_pool
    k_scan1<<<nbS, SCAN_B>>>(N);
    k_scan23<<<nbS, SCAN_B>>>(N);
    k_scatter<<<nbE, 256>>>(ei, elen, esh, x, E);

    // Layers (dst-major, fused norm-act)
    k_layer1<<<nbW, 256>>>(E, N);
    k_layer2<<<nbW, 256>>>(E, N);
    k_layer3<<<nbW, 256>>>(batch, E, N);
    k_head<<<1, 256>>>(Wo, bo, (float*)d_out);
}